// round 7
// baseline (speedup 1.0000x reference)
#include <cuda_runtime.h>
#include <cstdint>
#include <math.h>

#define D_MODEL 4096
#define N_HEADS 16
#define D_HEAD  256
#define ROTARY  64
#define D_FF    16384
#define BATCH   2
#define SEQ     2048
#define NROWS   (BATCH*SEQ)   /* 4096 */

#define BK 32
#define STAGES 3
#define A_STRIDE 36            /* BK + 4 pad; row = 144B (16B-aligned, LDSM conflict-free) */
#define BSTG (128 * A_STRIDE)  /* per-stage B elems: 128 n-rows */

// ---------------------------------------------------------------------------
// Scratch (static device globals; no allocation allowed)
// ---------------------------------------------------------------------------
__device__ __align__(16) float g_xn [(size_t)NROWS * D_MODEL];
__device__ __align__(16) float g_q  [(size_t)NROWS * D_MODEL];
__device__ __align__(16) float g_k  [(size_t)NROWS * D_MODEL];
__device__ __align__(16) float g_v  [(size_t)NROWS * D_MODEL];
__device__ __align__(16) float g_ctx[(size_t)NROWS * D_MODEL];
__device__ __align__(16) float g_x2 [(size_t)NROWS * D_MODEL];
__device__ __align__(16) float g_xn2[(size_t)NROWS * D_MODEL];
__device__ __align__(16) float g_sc [(size_t)BATCH * N_HEADS * SEQ * SEQ];  // 512 MB
__device__ __align__(16) float g_h  [(size_t)NROWS * D_FF];                 // 256 MB
__device__ __align__(16) float g_wr [(size_t)201326592];                    // 768 MB tf32 W^T

// ---------------------------------------------------------------------------
// Helpers
// ---------------------------------------------------------------------------
__device__ __forceinline__ uint32_t f2tf32(float f) {
    uint32_t u;
    asm("cvt.rna.tf32.f32 %0, %1;" : "=r"(u) : "f"(f));
    return u;
}
__device__ __forceinline__ float rtf(float f) { return __uint_as_float(f2tf32(f)); }
__device__ __forceinline__ float gelu_f(float x) {
    return 0.5f * x * (1.0f + tanhf(0.7978845608028654f * (x + 0.044715f * x * x * x)));
}
__device__ __forceinline__ void cp16(uint32_t dst, const float* src) {
    asm volatile("cp.async.cg.shared.global [%0], [%1], 16;\n" :: "r"(dst), "l"(src));
}
__device__ __forceinline__ void cp_commit() {
    asm volatile("cp.async.commit_group;\n" ::: "memory");
}
__device__ __forceinline__ void cp_wait1() {
    asm volatile("cp.async.wait_group 1;\n" ::: "memory");
}
__device__ __forceinline__ void ldsm4(uint32_t& r0, uint32_t& r1, uint32_t& r2, uint32_t& r3,
                                      uint32_t addr) {
    asm volatile("ldmatrix.sync.aligned.m8n8.x4.shared.b16 {%0,%1,%2,%3}, [%4];"
                 : "=r"(r0), "=r"(r1), "=r"(r2), "=r"(r3) : "r"(addr));
}

// ---------------------------------------------------------------------------
// Transpose + round to tf32: out[c][r] = rtf(in[r][c])
// ---------------------------------------------------------------------------
__global__ void transpose4_kernel(const float* __restrict__ w0, const float* __restrict__ w1,
                                  const float* __restrict__ w2, const float* __restrict__ w3,
                                  float* __restrict__ o0, float* __restrict__ o1,
                                  float* __restrict__ o2, float* __restrict__ o3)
{
    __shared__ float tile[32][33];
    const float* in; float* out;
    switch (blockIdx.z) {
        case 0: in = w0; out = o0; break;
        case 1: in = w1; out = o1; break;
        case 2: in = w2; out = o2; break;
        default: in = w3; out = o3; break;
    }
    int x = blockIdx.x * 32 + threadIdx.x;
    int y = blockIdx.y * 32 + threadIdx.y;
#pragma unroll
    for (int j = 0; j < 32; j += 8)
        tile[threadIdx.y + j][threadIdx.x] = in[(size_t)(y + j) * 4096 + x];
    __syncthreads();
    x = blockIdx.y * 32 + threadIdx.x;
    y = blockIdx.x * 32 + threadIdx.y;
#pragma unroll
    for (int j = 0; j < 32; j += 8)
        out[(size_t)(y + j) * 4096 + x] = rtf(tile[threadIdx.x][threadIdx.y + j]);
}

__global__ void transpose_rc_kernel(const float* __restrict__ in, float* __restrict__ out,
                                    int R, int C)
{
    __shared__ float tile[32][33];
    int x = blockIdx.x * 32 + threadIdx.x;    // col in [0,C)
    int y = blockIdx.y * 32 + threadIdx.y;    // row in [0,R)
#pragma unroll
    for (int j = 0; j < 32; j += 8)
        tile[threadIdx.y + j][threadIdx.x] = in[(size_t)(y + j) * C + x];
    __syncthreads();
    x = blockIdx.y * 32 + threadIdx.x;        // col in [0,R)
    y = blockIdx.x * 32 + threadIdx.y;        // row in [0,C)
#pragma unroll
    for (int j = 0; j < 32; j += 8)
        out[(size_t)(y + j) * R + x] = rtf(tile[threadIdx.x][threadIdx.y + j]);
}

// ---------------------------------------------------------------------------
// LayerNorm: one block per row; output rounded to tf32
// ---------------------------------------------------------------------------
__global__ void layernorm_kernel(const float* __restrict__ x,
                                 const float* __restrict__ scale,
                                 const float* __restrict__ offset,
                                 float* __restrict__ out)
{
    int row = blockIdx.x;
    const float4* xr = reinterpret_cast<const float4*>(x + (size_t)row * D_MODEL);
    float4 vals[4];
    float s = 0.f, sq = 0.f;
#pragma unroll
    for (int p = 0; p < 4; p++) {
        float4 v = xr[threadIdx.x + p * 256];
        vals[p] = v;
        s  += v.x + v.y + v.z + v.w;
        sq += v.x*v.x + v.y*v.y + v.z*v.z + v.w*v.w;
    }
    __shared__ float shm[64];
#pragma unroll
    for (int o = 16; o > 0; o >>= 1) {
        s  += __shfl_xor_sync(0xffffffffu, s,  o);
        sq += __shfl_xor_sync(0xffffffffu, sq, o);
    }
    int w = threadIdx.x >> 5;
    if ((threadIdx.x & 31) == 0) { shm[w] = s; shm[w + 32] = sq; }
    __syncthreads();
    if (threadIdx.x < 32) {
        float a = (threadIdx.x < 8) ? shm[threadIdx.x]      : 0.f;
        float b = (threadIdx.x < 8) ? shm[32 + threadIdx.x] : 0.f;
#pragma unroll
        for (int o = 4; o > 0; o >>= 1) {
            a += __shfl_xor_sync(0xffffffffu, a, o);
            b += __shfl_xor_sync(0xffffffffu, b, o);
        }
        if (threadIdx.x == 0) { shm[0] = a; shm[1] = b; }
    }
    __syncthreads();
    float mean = shm[0] * (1.0f / D_MODEL);
    float var  = shm[1] * (1.0f / D_MODEL) - mean * mean;
    float inv  = rsqrtf(var + 1e-5f);
    const float4* sc4 = reinterpret_cast<const float4*>(scale);
    const float4* of4 = reinterpret_cast<const float4*>(offset);
    float4* o4 = reinterpret_cast<float4*>(out + (size_t)row * D_MODEL);
#pragma unroll
    for (int p = 0; p < 4; p++) {
        int i = threadIdx.x + p * 256;
        float4 v = vals[p], g = sc4[i], b = of4[i], r;
        r.x = rtf((v.x - mean) * inv * g.x + b.x);
        r.y = rtf((v.y - mean) * inv * g.y + b.y);
        r.z = rtf((v.z - mean) * inv * g.z + b.z);
        r.w = rtf((v.w - mean) * inv * g.w + b.w);
        o4[i] = r;
    }
}

// ---------------------------------------------------------------------------
// RoPE (rounds rotated outputs back to tf32)
// ---------------------------------------------------------------------------
__global__ void rope_kernel(float* __restrict__ q, float* __restrict__ k)
{
    const int HALF = ROTARY / 2;
    int idx = blockIdx.x * blockDim.x + threadIdx.x;
    int total = NROWS * N_HEADS * HALF;
    if (idx >= total) return;
    int i  = idx % HALF;
    int h  = (idx / HALF) % N_HEADS;
    int bt = idx / (HALF * N_HEADS);
    int t  = bt % SEQ;

    float inv_freq = powf(10000.0f, -(float)i / (float)HALF);
    float fr = (float)t * inv_freq;
    float sn, cs;
    sincosf(fr, &sn, &cs);

    size_t base = (size_t)bt * D_MODEL + (size_t)h * D_HEAD + 2 * i;
    float x1 = q[base], x2 = q[base + 1];
    q[base]     = rtf(x1 * cs - x2 * sn);
    q[base + 1] = rtf(x2 * cs + x1 * sn);
    x1 = k[base]; x2 = k[base + 1];
    k[base]     = rtf(x1 * cs - x2 * sn);
    k[base + 1] = rtf(x2 * cs + x1 * sn);
}

// ---------------------------------------------------------------------------
// Causal softmax, in-place; writes tf32-rounded probabilities.
// Skips chunks beyond the causal tile boundary (never read by ctx GEMM).
// ---------------------------------------------------------------------------
__global__ void softmax_kernel(float* __restrict__ scores)
{
    size_t r = blockIdx.x;
    int t = blockIdx.x % SEQ;
    float* row = scores + r * SEQ;
    const float sc = 1.0f / 16.0f;
    int bound = ((t >> 7) + 1) << 7;

    float v[8];
    float mx = -1e30f;
#pragma unroll
    for (int j = 0; j < 8; j++) {
        int col = threadIdx.x + j * 256;
        float xv = (col <= t) ? row[col] * sc : -1e30f;
        v[j] = xv;
        mx = fmaxf(mx, xv);
    }
    __shared__ float shm[32];
#pragma unroll
    for (int o = 16; o > 0; o >>= 1) mx = fmaxf(mx, __shfl_xor_sync(0xffffffffu, mx, o));
    if ((threadIdx.x & 31) == 0) shm[threadIdx.x >> 5] = mx;
    __syncthreads();
    if (threadIdx.x < 32) {
        float m = (threadIdx.x < 8) ? shm[threadIdx.x] : -1e30f;
#pragma unroll
        for (int o = 4; o > 0; o >>= 1) m = fmaxf(m, __shfl_xor_sync(0xffffffffu, m, o));
        if (threadIdx.x == 0) shm[0] = m;
    }
    __syncthreads();
    mx = shm[0];
    __syncthreads();

    float s = 0.f;
#pragma unroll
    for (int j = 0; j < 8; j++) { float e = expf(v[j] - mx); v[j] = e; s += e; }
#pragma unroll
    for (int o = 16; o > 0; o >>= 1) s += __shfl_xor_sync(0xffffffffu, s, o);
    if ((threadIdx.x & 31) == 0) shm[threadIdx.x >> 5] = s;
    __syncthreads();
    if (threadIdx.x < 32) {
        float a = (threadIdx.x < 8) ? shm[threadIdx.x] : 0.f;
#pragma unroll
        for (int o = 4; o > 0; o >>= 1) a += __shfl_xor_sync(0xffffffffu, a, o);
        if (threadIdx.x == 0) shm[0] = a;
    }
    __syncthreads();
    float inv = 1.0f / shm[0];
#pragma unroll
    for (int j = 0; j < 8; j++) {
        if (j * 256 < bound)
            row[threadIdx.x + j * 256] = rtf(v[j] * inv);
    }
}

// ---------------------------------------------------------------------------
// ldmatrix TF32 GEMM: C[M,N] = A[M,K] @ Bt[N,K]^T (+epi)
//   Both operands k-contiguous in gmem (Bt pre-transposed) AND in smem, so all
//   fragments load via ldmatrix.m8n8.x4.b16 (8 LDSM per warp-kk vs 32 LDS.32).
//   cp.async 3-stage pipeline. CTA = BMT x 128, warp grid 4x2.
//   EPI: 0 none | 1 bias+gelu | 2 +Res | 3 bias+Res.
// ---------------------------------------------------------------------------
template<int BMT, int EPI, bool ROUNDOUT, bool CAUSAL_SKIP>
__global__ void __launch_bounds__(256)
gemm_ldsm(const float* __restrict__ A, const float* __restrict__ Bt,
          float* __restrict__ C,
          const float* __restrict__ bias, const float* __restrict__ Res,
          int K, int lda, int ldb, int ldc,
          long sAb, long sBb, long sCb, int Hb)
{
    constexpr int MT   = BMT / 128;
    constexpr int ASTG = BMT * A_STRIDE;

    int m0 = blockIdx.y * BMT;
    int n0 = blockIdx.x * 128;
    if (CAUSAL_SKIP) { if (n0 > m0 + BMT - 1) return; }

    int z = blockIdx.z;
    int b = z / Hb, hh = z % Hb;
    A  += (size_t)b * sAb + (size_t)hh * (size_t)D_HEAD;
    Bt += (size_t)b * sBb + (size_t)hh * (size_t)D_HEAD;
    C  += (size_t)b * sCb + (size_t)hh * (size_t)SEQ * SEQ * 0;  // (attention C has no head col-offset)
    if (Hb > 1) C += (size_t)hh * (size_t)SEQ * SEQ;             // per-head score planes

    extern __shared__ float smem_dyn[];
    float* AsF = smem_dyn;
    float* BsF = smem_dyn + STAGES * ASTG;
    uint32_t aBase = (uint32_t)__cvta_generic_to_shared(AsF);
    uint32_t bBase = (uint32_t)__cvta_generic_to_shared(BsF);

    int tid = threadIdx.x;
    int lane = tid & 31, warp = tid >> 5;
    int wm = warp & 3, wn = warp >> 2;
    int g  = lane >> 2, tg = lane & 3;
    int rlow = lane & 15, khalf = lane >> 4;

    float acc[2 * MT][8][4] = {};

    int KT = K / BK;

    int ar = tid >> 3, aq = tid & 7;

    auto loadTile = [&](int kt, int s) {
        const float* Ap = A + (size_t)(m0 + ar) * lda + (size_t)kt * BK + aq * 4;
#pragma unroll
        for (int p = 0; p < BMT / 32; p++)
            cp16(aBase + ((s * ASTG + (ar + p * 32) * A_STRIDE + aq * 4) << 2),
                 Ap + (size_t)p * 32 * lda);
        const float* Bp = Bt + (size_t)(n0 + ar) * ldb + (size_t)kt * BK + aq * 4;
#pragma unroll
        for (int p = 0; p < 4; p++)
            cp16(bBase + ((s * BSTG + (ar + p * 32) * A_STRIDE + aq * 4) << 2),
                 Bp + (size_t)p * 32 * ldb);
    };

    loadTile(0, 0); cp_commit();
    if (KT > 1) loadTile(1, 1);
    cp_commit();

    // Per-thread LDSM base offsets (bytes), before stage/kk adjustment:
    //   quad layout: lanes 0-15 -> rows base+(lane&15), k-cols 0-3;
    //                lanes 16-31 -> same rows, k-cols 4-7.
    uint32_t aoff0 = (uint32_t)(((wm * (32 * MT) + rlow) * A_STRIDE + khalf * 4) << 2);
    uint32_t boff0 = (uint32_t)(((wn * 64        + rlow) * A_STRIDE + khalf * 4) << 2);

    for (int kt = 0; kt < KT; kt++) {
        cp_wait1();
        __syncthreads();
        int s = kt % STAGES;
        uint32_t aS = aBase + ((uint32_t)(s * ASTG) << 2) + aoff0;
        uint32_t bS = bBase + ((uint32_t)(s * BSTG) << 2) + boff0;

#pragma unroll
        for (int kk = 0; kk < 4; kk++) {
            uint32_t af[2 * MT][4], bf[8][2];
#pragma unroll
            for (int mt = 0; mt < MT; mt++) {
                // one x4 per m16 block: quads = (m0-7,k0-3),(m8-15,k0-3),(m0-7,k4-7),(m8-15,k4-7)
                ldsm4(af[2*mt+0][0], af[2*mt+0][1], af[2*mt+0][2], af[2*mt+0][3],
                      aS + (uint32_t)((2*mt) * 16 * A_STRIDE * 4) + kk * 32);
                ldsm4(af[2*mt+1][0], af[2*mt+1][1], af[2*mt+1][2], af[2*mt+1][3],
                      aS + (uint32_t)((2*mt+1) * 16 * A_STRIDE * 4) + kk * 32);
            }
#pragma unroll
            for (int ntp = 0; ntp < 4; ntp++) {
                // one x4 per 2 n-tiles: r0=b[2p][0], r1=b[2p+1][0], r2=b[2p][1], r3=b[2p+1][1]
                ldsm4(bf[2*ntp][0], bf[2*ntp+1][0], bf[2*ntp][1], bf[2*ntp+1][1],
                      bS + (uint32_t)(ntp * 16 * A_STRIDE * 4) + kk * 32);
            }
#pragma unroll
            for (int mt = 0; mt < 2 * MT; mt++)
#pragma unroll
                for (int nt = 0; nt < 8; nt++) {
                    asm volatile(
                        "mma.sync.aligned.m16n8k8.row.col.f32.tf32.tf32.f32 "
                        "{%0,%1,%2,%3}, {%4,%5,%6,%7}, {%8,%9}, {%0,%1,%2,%3};\n"
                        : "+f"(acc[mt][nt][0]), "+f"(acc[mt][nt][1]),
                          "+f"(acc[mt][nt][2]), "+f"(acc[mt][nt][3])
                        : "r"(af[mt][0]), "r"(af[mt][1]), "r"(af[mt][2]), "r"(af[mt][3]),
                          "r"(bf[nt][0]), "r"(bf[nt][1]));
                }
        }

        if (kt + 2 < KT) loadTile(kt + 2, (kt + 2) % STAGES);
        cp_commit();
    }

    // Epilogue (float2 stores)
#pragma unroll
    for (int mt = 0; mt < 2 * MT; mt++) {
#pragma unroll
        for (int nt = 0; nt < 8; nt++) {
            int row0 = m0 + wm * (32 * MT) + mt * 16 + g;
            int col  = n0 + wn * 64 + nt * 8 + 2 * tg;
#pragma unroll
            for (int rr = 0; rr < 2; rr++) {
                int row = row0 + rr * 8;
                float v0 = acc[mt][nt][rr * 2 + 0];
                float v1 = acc[mt][nt][rr * 2 + 1];
                if (EPI == 1) {
                    v0 = gelu_f(v0 + bias[col]);
                    v1 = gelu_f(v1 + bias[col + 1]);
                } else if (EPI == 2) {
                    float2 rv = *reinterpret_cast<const float2*>(&Res[(size_t)row * ldc + col]);
                    v0 += rv.x; v1 += rv.y;
                } else if (EPI == 3) {
                    float2 rv = *reinterpret_cast<const float2*>(&Res[(size_t)row * ldc + col]);
                    v0 += bias[col] + rv.x; v1 += bias[col + 1] + rv.y;
                }
                if (ROUNDOUT) { v0 = rtf(v0); v1 = rtf(v1); }
                float2 ov; ov.x = v0; ov.y = v1;
                *reinterpret_cast<float2*>(&C[(size_t)row * ldc + col]) = ov;
            }
        }
    }
}

// ---------------------------------------------------------------------------
// Scalar-LDS TF32 GEMM (ctx = probs @ v only; B is [K,N] row-major)
// ---------------------------------------------------------------------------
#define B_STRIDE 136

__global__ void __launch_bounds__(256)
gemm_ctx(const float* __restrict__ A, const float* __restrict__ Bm,
         float* __restrict__ C,
         int K, int lda, int ldb, int ldc,
         long sAb, long sAh, long sBb, long sBh, long sCb, long sCh, int Hb)
{
    constexpr int ASTG = 128 * A_STRIDE;
    constexpr int BSTG2 = 32 * B_STRIDE;

    int m0 = blockIdx.y * 128;
    int n0 = blockIdx.x * 128;

    int z = blockIdx.z;
    int b = z / Hb, hh = z % Hb;
    A  += (size_t)b * sAb + (size_t)hh * sAh;
    Bm += (size_t)b * sBb + (size_t)hh * sBh;
    C  += (size_t)b * sCb + (size_t)hh * sCh;

    extern __shared__ float smem_dyn[];
    float* AsF = smem_dyn;
    float* BsF = smem_dyn + STAGES * ASTG;
    uint32_t aBase = (uint32_t)__cvta_generic_to_shared(AsF);
    uint32_t bBase = (uint32_t)__cvta_generic_to_shared(BsF);

    int tid = threadIdx.x;
    int lane = tid & 31, warp = tid >> 5;
    int wm = warp & 3, wn = warp >> 2;
    int g  = lane >> 2, tg = lane & 3;

    float acc[2][8][4] = {};

    int KT = K / BK;
    { int lim = (m0 + 128) / BK; if (lim < KT) KT = lim; }   // causal K-truncation

    int ar = tid >> 3, aq = tid & 7;
    int br = tid >> 5, bq = tid & 31;

    auto loadTile = [&](int kt, int s) {
        const float* Ap = A + (size_t)(m0 + ar) * lda + (size_t)kt * BK + aq * 4;
#pragma unroll
        for (int p = 0; p < 4; p++)
            cp16(aBase + ((s * ASTG + (ar + p * 32) * A_STRIDE + aq * 4) << 2),
                 Ap + (size_t)p * 32 * lda);
        const float* Bp = Bm + (size_t)(kt * BK + br) * ldb + n0 + bq * 4;
#pragma unroll
        for (int p = 0; p < 4; p++)
            cp16(bBase + ((s * BSTG2 + (br + p * 8) * B_STRIDE + bq * 4) << 2),
                 Bp + (size_t)p * 8 * ldb);
    };

    loadTile(0, 0); cp_commit();
    if (KT > 1) loadTile(1, 1);
    cp_commit();

    for (int kt = 0; kt < KT; kt++) {
        cp_wait1();
        __syncthreads();
        int s = kt % STAGES;
        const uint32_t* Ast = reinterpret_cast<const uint32_t*>(AsF + s * ASTG);
        const uint32_t* Bst = reinterpret_cast<const uint32_t*>(BsF + s * BSTG2);

#pragma unroll
        for (int kk = 0; kk < 4; kk++) {
            uint32_t af[2][4], bf[8][2];
#pragma unroll
            for (int mt = 0; mt < 2; mt++) {
                int r0 = wm * 32 + mt * 16 + g;
                af[mt][0] = Ast[r0 * A_STRIDE + kk * 8 + tg];
                af[mt][1] = Ast[(r0 + 8) * A_STRIDE + kk * 8 + tg];
                af[mt][2] = Ast[r0 * A_STRIDE + kk * 8 + tg + 4];
                af[mt][3] = Ast[(r0 + 8) * A_STRIDE + kk * 8 + tg + 4];
            }
#pragma unroll
            for (int nt = 0; nt < 8; nt++) {
                int c0 = wn * 64 + nt * 8 + g;
                bf[nt][0] = Bst[(kk * 8 + tg) * B_STRIDE + c0];
                bf[nt][1] = Bst[(kk * 8 + tg + 4) * B_STRIDE + c0];
            }
#pragma unroll
            for (int mt = 0; mt < 2; mt++)
#pragma unroll
                for (int nt = 0; nt < 8; nt++) {
                    asm volatile(
                        "mma.sync.aligned.m16n8k8.row.col.f32.tf32.tf32.f32 "
                        "{%0,%1,%2,%3}, {%4,%5,%6,%7}, {%8,%9}, {%0,%1,%2,%3};\n"
                        : "+f"(acc[mt][nt][0]), "+f"(acc[mt][nt][1]),
                          "+f"(acc[mt][nt][2]), "+f"(acc[mt][nt][3])
                        : "r"(af[mt][0]), "r"(af[mt][1]), "r"(af[mt][2]), "r"(af[mt][3]),
                          "r"(bf[nt][0]), "r"(bf[nt][1]));
                }
        }

        if (kt + 2 < KT) loadTile(kt + 2, (kt + 2) % STAGES);
        cp_commit();
    }

#pragma unroll
    for (int mt = 0; mt < 2; mt++) {
#pragma unroll
        for (int nt = 0; nt < 8; nt++) {
            int row0 = m0 + wm * 32 + mt * 16 + g;
            int col  = n0 + wn * 64 + nt * 8 + 2 * tg;
#pragma unroll
            for (int rr = 0; rr < 2; rr++) {
                int row = row0 + rr * 8;
                float2 ov;
                ov.x = rtf(acc[mt][nt][rr * 2 + 0]);
                ov.y = rtf(acc[mt][nt][rr * 2 + 1]);
                *reinterpret_cast<float2*>(&C[(size_t)row * ldc + col]) = ov;
            }
        }
    }
}

// ---------------------------------------------------------------------------
// Launch
// ---------------------------------------------------------------------------
extern "C" void kernel_launch(void* const* d_in, const int* in_sizes, int n_in,
                              void* d_out, int out_size)
{
    (void)in_sizes; (void)n_in; (void)out_size;
    const float* x     = (const float*)d_in[0];
    const float* lns   = (const float*)d_in[1];
    const float* lno   = (const float*)d_in[2];
    const float* wq    = (const float*)d_in[3];
    const float* wk    = (const float*)d_in[4];
    const float* wv    = (const float*)d_in[5];
    const float* wo    = (const float*)d_in[6];
    const float* w_in  = (const float*)d_in[7];
    const float* b_in  = (const float*)d_in[8];
    const float* w_out = (const float*)d_in[9];
    const float* b_out = (const float*)d_in[10];
    float* out = (float*)d_out;

    float *xn, *q, *k, *v, *sc, *ctx, *x2, *xn2, *hbuf, *wr;
    cudaGetSymbolAddress((void**)&xn,   g_xn);
    cudaGetSymbolAddress((void**)&q,    g_q);
    cudaGetSymbolAddress((void**)&k,    g_k);
    cudaGetSymbolAddress((void**)&v,    g_v);
    cudaGetSymbolAddress((void**)&sc,   g_sc);
    cudaGetSymbolAddress((void**)&ctx,  g_ctx);
    cudaGetSymbolAddress((void**)&x2,   g_x2);
    cudaGetSymbolAddress((void**)&xn2,  g_xn2);
    cudaGetSymbolAddress((void**)&hbuf, g_h);
    cudaGetSymbolAddress((void**)&wr,   g_wr);

    const size_t WSZ = (size_t)D_MODEL * D_MODEL;
    float* wqT  = wr;
    float* wkT  = wr + WSZ;
    float* wvT  = wr + 2 * WSZ;
    float* woT  = wr + 3 * WSZ;
    float* winT = wr + 4 * WSZ;                          // [D_FF, D_MODEL]
    float* wouT = winT + (size_t)D_MODEL * D_FF;         // [D_MODEL, D_FF]

    const int SM256 = STAGES * (256 * A_STRIDE + BSTG) * 4;          // 165,888
    const int SM128 = STAGES * (128 * A_STRIDE + BSTG) * 4;          // 110,592
    const int SMCTX = STAGES * (128 * A_STRIDE + 32 * B_STRIDE) * 4; // 107,520

    cudaFuncSetAttribute(gemm_ldsm<256,0,true ,false>, cudaFuncAttributeMaxDynamicSharedMemorySize, SM256);
    cudaFuncSetAttribute(gemm_ldsm<256,2,false,false>, cudaFuncAttributeMaxDynamicSharedMemorySize, SM256);
    cudaFuncSetAttribute(gemm_ldsm<256,1,true ,false>, cudaFuncAttributeMaxDynamicSharedMemorySize, SM256);
    cudaFuncSetAttribute(gemm_ldsm<256,3,false,false>, cudaFuncAttributeMaxDynamicSharedMemorySize, SM256);
    cudaFuncSetAttribute(gemm_ldsm<128,0,false,true >, cudaFuncAttributeMaxDynamicSharedMemorySize, SM128);
    cudaFuncSetAttribute(gemm_ctx, cudaFuncAttributeMaxDynamicSharedMemorySize, SMCTX);

    dim3 tb(32, 8);

    // 1-3. Transpose + tf32-round all weights into [N,K]
    transpose4_kernel<<<dim3(128, 128, 4), tb>>>(wq, wk, wv, wo, wqT, wkT, wvT, woT);
    transpose_rc_kernel<<<dim3(D_FF / 32, D_MODEL / 32), tb>>>(w_in,  winT, D_MODEL, D_FF);
    transpose_rc_kernel<<<dim3(D_MODEL / 32, D_FF / 32), tb>>>(w_out, wouT, D_FF, D_MODEL);

    // 4. LayerNorm (emits tf32)
    layernorm_kernel<<<NROWS, 256>>>(x, lns, lno, xn);

    // 5-7. QKV projections (ldsm path; outputs tf32)
    dim3 gP(D_MODEL / 128, NROWS / 256, 1);
    gemm_ldsm<256,0,true ,false><<<gP, 256, SM256>>>(xn, wqT, q, nullptr, nullptr,
        D_MODEL, D_MODEL, D_MODEL, D_MODEL, 0, 0, 0, 1);
    gemm_ldsm<256,0,true ,false><<<gP, 256, SM256>>>(xn, wkT, k, nullptr, nullptr,
        D_MODEL, D_MODEL, D_MODEL, D_MODEL, 0, 0, 0, 1);
    gemm_ldsm<256,0,true ,false><<<gP, 256, SM256>>>(xn, wvT, v, nullptr, nullptr,
        D_MODEL, D_MODEL, D_MODEL, D_MODEL, 0, 0, 0, 1);

    // 8. RoPE
    {
        int total = NROWS * N_HEADS * (ROTARY / 2);
        rope_kernel<<<(total + 255) / 256, 256>>>(q, k);
    }

    // 9. scores = q @ k^T (ldsm path; causal tile-skip; batched b,h)
    dim3 gS(SEQ / 128, SEQ / 128, BATCH * N_HEADS);
    gemm_ldsm<128,0,false,true ><<<gS, 256, SM128>>>(q, k, sc, nullptr, nullptr,
        D_HEAD, D_MODEL, D_MODEL, SEQ,
        (long)SEQ * D_MODEL, (long)SEQ * D_MODEL,
        (long)N_HEADS * SEQ * SEQ, N_HEADS);

    // 10. causal softmax (emits tf32 probs)
    softmax_kernel<<<BATCH * N_HEADS * SEQ, 256>>>(sc);

    // 11. ctx = probs @ v (scalar-LDS NN; K truncated; rounds output)
    dim3 gC(D_HEAD / 128, SEQ / 128, BATCH * N_HEADS);
    gemm_ctx<<<gC, 256, SMCTX>>>(sc, v, ctx,
        SEQ, SEQ, D_MODEL, D_MODEL,
        (long)N_HEADS * SEQ * SEQ, (long)SEQ * SEQ,
        (long)SEQ * D_MODEL, (long)D_HEAD,
        (long)SEQ * D_MODEL, (long)D_HEAD, N_HEADS);

    // 12. x2 = x + ctx @ wo (ldsm path, fp32 residual)
    gemm_ldsm<256,2,false,false><<<gP, 256, SM256>>>(ctx, woT, x2, nullptr, x,
        D_MODEL, D_MODEL, D_MODEL, D_MODEL, 0, 0, 0, 1);

    // 13. LayerNorm 2 (emits tf32)
    layernorm_kernel<<<NROWS, 256>>>(x2, lns, lno, xn2);

    // 14. h = gelu(xn2 @ w_in + b_in) (ldsm path; rounds output)
    dim3 gF(D_FF / 128, NROWS / 256, 1);
    gemm_ldsm<256,1,true ,false><<<gF, 256, SM256>>>(xn2, winT, hbuf, b_in, nullptr,
        D_MODEL, D_MODEL, D_MODEL, D_FF, 0, 0, 0, 1);

    // 15. out = x2 + h @ w_out + b_out (ldsm path)
    gemm_ldsm<256,3,false,false><<<gP, 256, SM256>>>(hbuf, wouT, out, b_out, x2,
        D_FF, D_FF, D_FF, D_MODEL, 0, 0, 0, 1);
}

// round 8
// speedup vs baseline: 1.9190x; 1.9190x over previous
#include <cuda_runtime.h>
#include <cuda_fp16.h>
#include <cstdint>
#include <math.h>

#define D_MODEL 4096
#define N_HEADS 16
#define D_HEAD  256
#define ROTARY  64
#define D_FF    16384
#define BATCH   2
#define SEQ     2048
#define NROWS   (BATCH*SEQ)   /* 4096 */

#define STAGES 3
/* fp16 GEMM: BK=64 halfs, row stride 72 halfs = 144B (LDSM conflict-free) */
#define HS 72
#define ROWB 144

// ---------------------------------------------------------------------------
// Scratch (static device globals; no allocation allowed)
// ---------------------------------------------------------------------------
__device__ __align__(16) __half g_xn [(size_t)NROWS * D_MODEL];
__device__ __align__(16) __half g_xn2[(size_t)NROWS * D_MODEL];
__device__ __align__(16) __half g_q  [(size_t)NROWS * D_MODEL];
__device__ __align__(16) __half g_k  [(size_t)NROWS * D_MODEL];
__device__ __align__(16) __half g_ctx[(size_t)NROWS * D_MODEL];
__device__ __align__(16) __half g_h  [(size_t)NROWS * D_FF];
__device__ __align__(16) __half g_wh [(size_t)201326592];                   // 384 MB W^T fp16
__device__ __align__(16) float  g_v  [(size_t)NROWS * D_MODEL];
__device__ __align__(16) float  g_x2 [(size_t)NROWS * D_MODEL];
__device__ __align__(16) float  g_sc [(size_t)BATCH * N_HEADS * SEQ * SEQ]; // 512 MB

// ---------------------------------------------------------------------------
// Helpers
// ---------------------------------------------------------------------------
__device__ __forceinline__ uint32_t f2tf32(float f) {
    uint32_t u;
    asm("cvt.rna.tf32.f32 %0, %1;" : "=r"(u) : "f"(f));
    return u;
}
__device__ __forceinline__ float rtf(float f) { return __uint_as_float(f2tf32(f)); }
__device__ __forceinline__ float gelu_f(float x) {
    return 0.5f * x * (1.0f + tanhf(0.7978845608028654f * (x + 0.044715f * x * x * x)));
}
__device__ __forceinline__ void cp16(uint32_t dst, const void* src) {
    asm volatile("cp.async.cg.shared.global [%0], [%1], 16;\n" :: "r"(dst), "l"(src));
}
__device__ __forceinline__ void cp_commit() {
    asm volatile("cp.async.commit_group;\n" ::: "memory");
}
__device__ __forceinline__ void cp_wait1() {
    asm volatile("cp.async.wait_group 1;\n" ::: "memory");
}
__device__ __forceinline__ void ldsm4(uint32_t& r0, uint32_t& r1, uint32_t& r2, uint32_t& r3,
                                      uint32_t addr) {
    asm volatile("ldmatrix.sync.aligned.m8n8.x4.shared.b16 {%0,%1,%2,%3}, [%4];"
                 : "=r"(r0), "=r"(r1), "=r"(r2), "=r"(r3) : "r"(addr));
}

// ---------------------------------------------------------------------------
// Transpose + convert: out[c][r] = half(in[r][c])
// ---------------------------------------------------------------------------
__global__ void transpose4_kernel(const float* __restrict__ w0, const float* __restrict__ w1,
                                  const float* __restrict__ w2, const float* __restrict__ w3,
                                  __half* __restrict__ o0, __half* __restrict__ o1,
                                  __half* __restrict__ o2, __half* __restrict__ o3)
{
    __shared__ float tile[32][33];
    const float* in; __half* out;
    switch (blockIdx.z) {
        case 0: in = w0; out = o0; break;
        case 1: in = w1; out = o1; break;
        case 2: in = w2; out = o2; break;
        default: in = w3; out = o3; break;
    }
    int x = blockIdx.x * 32 + threadIdx.x;
    int y = blockIdx.y * 32 + threadIdx.y;
#pragma unroll
    for (int j = 0; j < 32; j += 8)
        tile[threadIdx.y + j][threadIdx.x] = in[(size_t)(y + j) * 4096 + x];
    __syncthreads();
    x = blockIdx.y * 32 + threadIdx.x;
    y = blockIdx.x * 32 + threadIdx.y;
#pragma unroll
    for (int j = 0; j < 32; j += 8)
        out[(size_t)(y + j) * 4096 + x] = __float2half_rn(tile[threadIdx.x][threadIdx.y + j]);
}

__global__ void transpose_rc_kernel(const float* __restrict__ in, __half* __restrict__ out,
                                    int R, int C)
{
    __shared__ float tile[32][33];
    int x = blockIdx.x * 32 + threadIdx.x;
    int y = blockIdx.y * 32 + threadIdx.y;
#pragma unroll
    for (int j = 0; j < 32; j += 8)
        tile[threadIdx.y + j][threadIdx.x] = in[(size_t)(y + j) * C + x];
    __syncthreads();
    x = blockIdx.y * 32 + threadIdx.x;
    y = blockIdx.x * 32 + threadIdx.y;
#pragma unroll
    for (int j = 0; j < 32; j += 8)
        out[(size_t)(y + j) * R + x] = __float2half_rn(tile[threadIdx.x][threadIdx.y + j]);
}

// ---------------------------------------------------------------------------
// LayerNorm: one block per row; emits fp16
// ---------------------------------------------------------------------------
__global__ void layernorm_kernel(const float* __restrict__ x,
                                 const float* __restrict__ scale,
                                 const float* __restrict__ offset,
                                 __half* __restrict__ out)
{
    int row = blockIdx.x;
    const float4* xr = reinterpret_cast<const float4*>(x + (size_t)row * D_MODEL);
    float4 vals[4];
    float s = 0.f, sq = 0.f;
#pragma unroll
    for (int p = 0; p < 4; p++) {
        float4 v = xr[threadIdx.x + p * 256];
        vals[p] = v;
        s  += v.x + v.y + v.z + v.w;
        sq += v.x*v.x + v.y*v.y + v.z*v.z + v.w*v.w;
    }
    __shared__ float shm[64];
#pragma unroll
    for (int o = 16; o > 0; o >>= 1) {
        s  += __shfl_xor_sync(0xffffffffu, s,  o);
        sq += __shfl_xor_sync(0xffffffffu, sq, o);
    }
    int w = threadIdx.x >> 5;
    if ((threadIdx.x & 31) == 0) { shm[w] = s; shm[w + 32] = sq; }
    __syncthreads();
    if (threadIdx.x < 32) {
        float a = (threadIdx.x < 8) ? shm[threadIdx.x]      : 0.f;
        float b = (threadIdx.x < 8) ? shm[32 + threadIdx.x] : 0.f;
#pragma unroll
        for (int o = 4; o > 0; o >>= 1) {
            a += __shfl_xor_sync(0xffffffffu, a, o);
            b += __shfl_xor_sync(0xffffffffu, b, o);
        }
        if (threadIdx.x == 0) { shm[0] = a; shm[1] = b; }
    }
    __syncthreads();
    float mean = shm[0] * (1.0f / D_MODEL);
    float var  = shm[1] * (1.0f / D_MODEL) - mean * mean;
    float inv  = rsqrtf(var + 1e-5f);
    const float4* sc4 = reinterpret_cast<const float4*>(scale);
    const float4* of4 = reinterpret_cast<const float4*>(offset);
    __half2* o2 = reinterpret_cast<__half2*>(out + (size_t)row * D_MODEL);
#pragma unroll
    for (int p = 0; p < 4; p++) {
        int i = threadIdx.x + p * 256;
        float4 v = vals[p], g = sc4[i], b = of4[i];
        float r0 = (v.x - mean) * inv * g.x + b.x;
        float r1 = (v.y - mean) * inv * g.y + b.y;
        float r2 = (v.z - mean) * inv * g.z + b.z;
        float r3 = (v.w - mean) * inv * g.w + b.w;
        o2[i * 2]     = __floats2half2_rn(r0, r1);
        o2[i * 2 + 1] = __floats2half2_rn(r2, r3);
    }
}

// ---------------------------------------------------------------------------
// RoPE on fp16 q, k (compute fp32, store fp16)
// ---------------------------------------------------------------------------
__global__ void rope_kernel(__half* __restrict__ q, __half* __restrict__ k)
{
    const int HALF = ROTARY / 2;
    int idx = blockIdx.x * blockDim.x + threadIdx.x;
    int total = NROWS * N_HEADS * HALF;
    if (idx >= total) return;
    int i  = idx % HALF;
    int h  = (idx / HALF) % N_HEADS;
    int bt = idx / (HALF * N_HEADS);
    int t  = bt % SEQ;

    float inv_freq = powf(10000.0f, -(float)i / (float)HALF);
    float fr = (float)t * inv_freq;
    float sn, cs;
    sincosf(fr, &sn, &cs);

    size_t base = (size_t)bt * D_MODEL + (size_t)h * D_HEAD + 2 * i;
    __half2* qp = reinterpret_cast<__half2*>(q + base);
    __half2* kp = reinterpret_cast<__half2*>(k + base);
    float2 qv = __half22float2(*qp);
    float2 kv = __half22float2(*kp);
    *qp = __floats2half2_rn(qv.x * cs - qv.y * sn, qv.y * cs + qv.x * sn);
    *kp = __floats2half2_rn(kv.x * cs - kv.y * sn, kv.y * cs + kv.x * sn);
}

// ---------------------------------------------------------------------------
// Causal softmax (fp32 in/out, tf32-rounded probs; skips never-read chunks)
// ---------------------------------------------------------------------------
__global__ void softmax_kernel(float* __restrict__ scores)
{
    size_t r = blockIdx.x;
    int t = blockIdx.x % SEQ;
    float* row = scores + r * SEQ;
    const float sc = 1.0f / 16.0f;
    int bound = ((t >> 7) + 1) << 7;

    float v[8];
    float mx = -1e30f;
#pragma unroll
    for (int j = 0; j < 8; j++) {
        int col = threadIdx.x + j * 256;
        float xv = (col <= t) ? row[col] * sc : -1e30f;
        v[j] = xv;
        mx = fmaxf(mx, xv);
    }
    __shared__ float shm[32];
#pragma unroll
    for (int o = 16; o > 0; o >>= 1) mx = fmaxf(mx, __shfl_xor_sync(0xffffffffu, mx, o));
    if ((threadIdx.x & 31) == 0) shm[threadIdx.x >> 5] = mx;
    __syncthreads();
    if (threadIdx.x < 32) {
        float m = (threadIdx.x < 8) ? shm[threadIdx.x] : -1e30f;
#pragma unroll
        for (int o = 4; o > 0; o >>= 1) m = fmaxf(m, __shfl_xor_sync(0xffffffffu, m, o));
        if (threadIdx.x == 0) shm[0] = m;
    }
    __syncthreads();
    mx = shm[0];
    __syncthreads();

    float s = 0.f;
#pragma unroll
    for (int j = 0; j < 8; j++) { float e = expf(v[j] - mx); v[j] = e; s += e; }
#pragma unroll
    for (int o = 16; o > 0; o >>= 1) s += __shfl_xor_sync(0xffffffffu, s, o);
    if ((threadIdx.x & 31) == 0) shm[threadIdx.x >> 5] = s;
    __syncthreads();
    if (threadIdx.x < 32) {
        float a = (threadIdx.x < 8) ? shm[threadIdx.x] : 0.f;
#pragma unroll
        for (int o = 4; o > 0; o >>= 1) a += __shfl_xor_sync(0xffffffffu, a, o);
        if (threadIdx.x == 0) shm[0] = a;
    }
    __syncthreads();
    float inv = 1.0f / shm[0];
#pragma unroll
    for (int j = 0; j < 8; j++) {
        if (j * 256 < bound)
            row[threadIdx.x + j * 256] = rtf(v[j] * inv);
    }
}

// ---------------------------------------------------------------------------
// FP16 tensor-core GEMM: C[M,N] = A[M,K] @ Bt[N,K]^T (+epi)
//   A, Bt fp16, both k-contiguous; m16n8k16 MMA, fragments via ldmatrix.b16.
//   cp.async 3-stage, BK=64 halfs (128B rows, stride 144B).
//   CTA = BMT x 128 (warp 64x64 for BMT=256, 32x64 for BMT=128).
//   EPI: 0 none | 1 bias+gelu | 2 +Res | 3 bias+Res
//   OUT: 0 f32 | 1 f32 tf32-rounded | 2 fp16
// ---------------------------------------------------------------------------
template<int BMT, int EPI, int OUT, bool CAUSAL_SKIP>
__global__ void __launch_bounds__(256)
gemm_h(const __half* __restrict__ A, const __half* __restrict__ Bt,
       void* __restrict__ Cv, const float* __restrict__ bias,
       const float* __restrict__ Res,
       int K, int lda, int ldb, int ldc,
       long sAb, long sAh, long sBb, long sBh, long sCb, long sCh, int Hb)
{
    constexpr int MT    = BMT / 128;        // 1 or 2
    constexpr int ASTGB = BMT * ROWB;       // stage bytes (A)
    constexpr int BSTGB = 128 * ROWB;

    int m0 = blockIdx.y * BMT;
    int n0 = blockIdx.x * 128;
    if (CAUSAL_SKIP) { if (n0 > m0 + BMT - 1) return; }

    int z = blockIdx.z;
    int b = z / Hb, hh = z % Hb;
    A  += (size_t)b * sAb + (size_t)hh * sAh;
    Bt += (size_t)b * sBb + (size_t)hh * sBh;
    float*  Cf = reinterpret_cast<float*>(Cv)  + (size_t)b * sCb + (size_t)hh * sCh;
    __half* Ch = reinterpret_cast<__half*>(Cv) + (size_t)b * sCb + (size_t)hh * sCh;

    extern __shared__ char smem_dyn[];
    uint32_t aBase = (uint32_t)__cvta_generic_to_shared(smem_dyn);
    uint32_t bBase = aBase + STAGES * ASTGB;

    int tid = threadIdx.x;
    int lane = tid & 31, warp = tid >> 5;
    int wm = warp & 3, wn = warp >> 2;
    int g  = lane >> 2, tg = lane & 3;

    float acc[2 * MT][8][4] = {};

    int KT = K >> 6;

    int lc = tid & 7, lr = tid >> 3;       // load: 8 chunks/row, 32 rows/pass

    auto loadTile = [&](int kt, int s) {
        const __half* ap = A + (size_t)m0 * lda + (size_t)kt * 64;
#pragma unroll
        for (int p = 0; p < BMT / 32; p++) {
            int row = lr + p * 32;
            cp16(aBase + (uint32_t)(s * ASTGB + row * ROWB + lc * 16),
                 ap + (size_t)row * lda + lc * 8);
        }
        const __half* bp = Bt + (size_t)n0 * ldb + (size_t)kt * 64;
#pragma unroll
        for (int p = 0; p < 4; p++) {
            int row = lr + p * 32;
            cp16(bBase + (uint32_t)(s * BSTGB + row * ROWB + lc * 16),
                 bp + (size_t)row * ldb + lc * 8);
        }
    };

    loadTile(0, 0); cp_commit();
    if (KT > 1) loadTile(1, 1);
    cp_commit();

    // ldmatrix per-lane address pieces
    int lane_row = (lane & 7) | (((lane >> 3) & 1) << 3);  // 0..15
    int lane_kb  = (lane >> 4) << 4;                        // 0 or 16 bytes
    uint32_t aoff0 = (uint32_t)((wm * (32 * MT) + lane_row) * ROWB + lane_kb);
    uint32_t boff0 = (uint32_t)((wn * 64        + lane_row) * ROWB + lane_kb);

    for (int kt = 0; kt < KT; kt++) {
        cp_wait1();
        __syncthreads();
        int s = kt % STAGES;
        uint32_t aS = aBase + (uint32_t)(s * ASTGB) + aoff0;
        uint32_t bS = bBase + (uint32_t)(s * BSTGB) + boff0;

#pragma unroll
        for (int kk = 0; kk < 4; kk++) {
            uint32_t af[2 * MT][4], bf[8][2];
            uint32_t kkb = kk * 32;
#pragma unroll
            for (int mt = 0; mt < 2 * MT; mt++)
                ldsm4(af[mt][0], af[mt][1], af[mt][2], af[mt][3],
                      aS + (uint32_t)(mt * 16 * ROWB) + kkb);
#pragma unroll
            for (int p = 0; p < 4; p++)
                ldsm4(bf[2*p][0], bf[2*p+1][0], bf[2*p][1], bf[2*p+1][1],
                      bS + (uint32_t)(p * 16 * ROWB) + kkb);
#pragma unroll
            for (int mt = 0; mt < 2 * MT; mt++)
#pragma unroll
                for (int nt = 0; nt < 8; nt++) {
                    asm volatile(
                        "mma.sync.aligned.m16n8k16.row.col.f32.f16.f16.f32 "
                        "{%0,%1,%2,%3}, {%4,%5,%6,%7}, {%8,%9}, {%0,%1,%2,%3};\n"
                        : "+f"(acc[mt][nt][0]), "+f"(acc[mt][nt][1]),
                          "+f"(acc[mt][nt][2]), "+f"(acc[mt][nt][3])
                        : "r"(af[mt][0]), "r"(af[mt][1]), "r"(af[mt][2]), "r"(af[mt][3]),
                          "r"(bf[nt][0]), "r"(bf[nt][1]));
                }
        }

        if (kt + 2 < KT) loadTile(kt + 2, (kt + 2) % STAGES);
        cp_commit();
    }

    // Epilogue
#pragma unroll
    for (int mt = 0; mt < 2 * MT; mt++) {
#pragma unroll
        for (int nt = 0; nt < 8; nt++) {
            int row0 = m0 + wm * (32 * MT) + mt * 16 + g;
            int col  = n0 + wn * 64 + nt * 8 + 2 * tg;
#pragma unroll
            for (int rr = 0; rr < 2; rr++) {
                int row = row0 + rr * 8;
                float v0 = acc[mt][nt][rr * 2 + 0];
                float v1 = acc[mt][nt][rr * 2 + 1];
                if (EPI == 1) {
                    v0 = gelu_f(v0 + bias[col]);
                    v1 = gelu_f(v1 + bias[col + 1]);
                } else if (EPI == 2) {
                    float2 rv = *reinterpret_cast<const float2*>(&Res[(size_t)row * ldc + col]);
                    v0 += rv.x; v1 += rv.y;
                } else if (EPI == 3) {
                    float2 rv = *reinterpret_cast<const float2*>(&Res[(size_t)row * ldc + col]);
                    v0 += bias[col] + rv.x; v1 += bias[col + 1] + rv.y;
                }
                if (OUT == 2) {
                    *reinterpret_cast<__half2*>(&Ch[(size_t)row * ldc + col]) =
                        __floats2half2_rn(v0, v1);
                } else {
                    if (OUT == 1) { v0 = rtf(v0); v1 = rtf(v1); }
                    float2 ov; ov.x = v0; ov.y = v1;
                    *reinterpret_cast<float2*>(&Cf[(size_t)row * ldc + col]) = ov;
                }
            }
        }
    }
}

// ---------------------------------------------------------------------------
// Scalar-LDS TF32 GEMM for ctx = probs @ v (B is [K,N] row-major, fp32).
// Proven round-5 kernel; output now fp16 (feeds WO GEMM A).
// ---------------------------------------------------------------------------
#define BK32 32
#define A_STRIDE 36
#define B_STRIDE 136

__global__ void __launch_bounds__(256)
gemm_ctx(const float* __restrict__ A, const float* __restrict__ Bm,
         __half* __restrict__ C,
         int K, int lda, int ldb, int ldc,
         long sAb, long sAh, long sBb, long sBh, long sCb, long sCh, int Hb)
{
    constexpr int ASTG = 128 * A_STRIDE;
    constexpr int BSTG2 = 32 * B_STRIDE;

    int m0 = blockIdx.y * 128;
    int n0 = blockIdx.x * 128;

    int z = blockIdx.z;
    int b = z / Hb, hh = z % Hb;
    A  += (size_t)b * sAb + (size_t)hh * sAh;
    Bm += (size_t)b * sBb + (size_t)hh * sBh;
    C  += (size_t)b * sCb + (size_t)hh * sCh;

    extern __shared__ float smem_dyn_f[];
    float* AsF = smem_dyn_f;
    float* BsF = smem_dyn_f + STAGES * ASTG;
    uint32_t aBase = (uint32_t)__cvta_generic_to_shared(AsF);
    uint32_t bBase = (uint32_t)__cvta_generic_to_shared(BsF);

    int tid = threadIdx.x;
    int lane = tid & 31, warp = tid >> 5;
    int wm = warp & 3, wn = warp >> 2;
    int g  = lane >> 2, tg = lane & 3;

    float acc[2][8][4] = {};

    int KT = K / BK32;
    { int lim = (m0 + 128) / BK32; if (lim < KT) KT = lim; }   // causal K-trunc

    int ar = tid >> 3, aq = tid & 7;
    int br = tid >> 5, bq = tid & 31;

    auto loadTile = [&](int kt, int s) {
        const float* Ap = A + (size_t)(m0 + ar) * lda + (size_t)kt * BK32 + aq * 4;
#pragma unroll
        for (int p = 0; p < 4; p++)
            cp16(aBase + ((s * ASTG + (ar + p * 32) * A_STRIDE + aq * 4) << 2),
                 Ap + (size_t)p * 32 * lda);
        const float* Bp = Bm + (size_t)(kt * BK32 + br) * ldb + n0 + bq * 4;
#pragma unroll
        for (int p = 0; p < 4; p++)
            cp16(bBase + ((s * BSTG2 + (br + p * 8) * B_STRIDE + bq * 4) << 2),
                 Bp + (size_t)p * 8 * ldb);
    };

    loadTile(0, 0); cp_commit();
    if (KT > 1) loadTile(1, 1);
    cp_commit();

    for (int kt = 0; kt < KT; kt++) {
        cp_wait1();
        __syncthreads();
        int s = kt % STAGES;
        const uint32_t* Ast = reinterpret_cast<const uint32_t*>(AsF + s * ASTG);
        const uint32_t* Bst = reinterpret_cast<const uint32_t*>(BsF + s * BSTG2);

#pragma unroll
        for (int kk = 0; kk < 4; kk++) {
            uint32_t af[2][4], bf[8][2];
#pragma unroll
            for (int mt = 0; mt < 2; mt++) {
                int r0 = wm * 32 + mt * 16 + g;
                af[mt][0] = Ast[r0 * A_STRIDE + kk * 8 + tg];
                af[mt][1] = Ast[(r0 + 8) * A_STRIDE + kk * 8 + tg];
                af[mt][2] = Ast[r0 * A_STRIDE + kk * 8 + tg + 4];
                af[mt][3] = Ast[(r0 + 8) * A_STRIDE + kk * 8 + tg + 4];
            }
#pragma unroll
            for (int nt = 0; nt < 8; nt++) {
                int c0 = wn * 64 + nt * 8 + g;
                bf[nt][0] = Bst[(kk * 8 + tg) * B_STRIDE + c0];
                bf[nt][1] = Bst[(kk * 8 + tg + 4) * B_STRIDE + c0];
            }
#pragma unroll
            for (int mt = 0; mt < 2; mt++)
#pragma unroll
                for (int nt = 0; nt < 8; nt++) {
                    asm volatile(
                        "mma.sync.aligned.m16n8k8.row.col.f32.tf32.tf32.f32 "
                        "{%0,%1,%2,%3}, {%4,%5,%6,%7}, {%8,%9}, {%0,%1,%2,%3};\n"
                        : "+f"(acc[mt][nt][0]), "+f"(acc[mt][nt][1]),
                          "+f"(acc[mt][nt][2]), "+f"(acc[mt][nt][3])
                        : "r"(af[mt][0]), "r"(af[mt][1]), "r"(af[mt][2]), "r"(af[mt][3]),
                          "r"(bf[nt][0]), "r"(bf[nt][1]));
                }
        }

        if (kt + 2 < KT) loadTile(kt + 2, (kt + 2) % STAGES);
        cp_commit();
    }

#pragma unroll
    for (int mt = 0; mt < 2; mt++) {
#pragma unroll
        for (int nt = 0; nt < 8; nt++) {
            int row0 = m0 + wm * 32 + mt * 16 + g;
            int col  = n0 + wn * 64 + nt * 8 + 2 * tg;
#pragma unroll
            for (int rr = 0; rr < 2; rr++) {
                int row = row0 + rr * 8;
                *reinterpret_cast<__half2*>(&C[(size_t)row * ldc + col]) =
                    __floats2half2_rn(acc[mt][nt][rr * 2 + 0], acc[mt][nt][rr * 2 + 1]);
            }
        }
    }
}

// ---------------------------------------------------------------------------
// Launch
// ---------------------------------------------------------------------------
extern "C" void kernel_launch(void* const* d_in, const int* in_sizes, int n_in,
                              void* d_out, int out_size)
{
    (void)in_sizes; (void)n_in; (void)out_size;
    const float* x     = (const float*)d_in[0];
    const float* lns   = (const float*)d_in[1];
    const float* lno   = (const float*)d_in[2];
    const float* wq    = (const float*)d_in[3];
    const float* wk    = (const float*)d_in[4];
    const float* wv    = (const float*)d_in[5];
    const float* wo    = (const float*)d_in[6];
    const float* w_in  = (const float*)d_in[7];
    const float* b_in  = (const float*)d_in[8];
    const float* w_out = (const float*)d_in[9];
    const float* b_out = (const float*)d_in[10];
    float* out = (float*)d_out;

    __half *xn, *xn2, *q, *k, *ctx, *hbuf, *wh;
    float *v, *x2, *sc;
    cudaGetSymbolAddress((void**)&xn,   g_xn);
    cudaGetSymbolAddress((void**)&xn2,  g_xn2);
    cudaGetSymbolAddress((void**)&q,    g_q);
    cudaGetSymbolAddress((void**)&k,    g_k);
    cudaGetSymbolAddress((void**)&ctx,  g_ctx);
    cudaGetSymbolAddress((void**)&hbuf, g_h);
    cudaGetSymbolAddress((void**)&wh,   g_wh);
    cudaGetSymbolAddress((void**)&v,    g_v);
    cudaGetSymbolAddress((void**)&x2,   g_x2);
    cudaGetSymbolAddress((void**)&sc,   g_sc);

    const size_t WSZ = (size_t)D_MODEL * D_MODEL;
    __half* wqT  = wh;
    __half* wkT  = wh + WSZ;
    __half* wvT  = wh + 2 * WSZ;
    __half* woT  = wh + 3 * WSZ;
    __half* winT = wh + 4 * WSZ;                    // [D_FF, D_MODEL]
    __half* wouT = winT + (size_t)D_MODEL * D_FF;   // [D_MODEL, D_FF]

    const int SMH256 = STAGES * (256 * ROWB + 128 * ROWB);           // 165,888
    const int SMH128 = STAGES * (128 * ROWB + 128 * ROWB);           // 110,592
    const int SMCTX  = STAGES * (128 * A_STRIDE + 32 * B_STRIDE) * 4; // 107,520

    cudaFuncSetAttribute(gemm_h<256,0,2,false>, cudaFuncAttributeMaxDynamicSharedMemorySize, SMH256);
    cudaFuncSetAttribute(gemm_h<256,0,1,false>, cudaFuncAttributeMaxDynamicSharedMemorySize, SMH256);
    cudaFuncSetAttribute(gemm_h<128,0,0,true >, cudaFuncAttributeMaxDynamicSharedMemorySize, SMH128);
    cudaFuncSetAttribute(gemm_h<256,2,0,false>, cudaFuncAttributeMaxDynamicSharedMemorySize, SMH256);
    cudaFuncSetAttribute(gemm_h<256,1,2,false>, cudaFuncAttributeMaxDynamicSharedMemorySize, SMH256);
    cudaFuncSetAttribute(gemm_h<256,3,0,false>, cudaFuncAttributeMaxDynamicSharedMemorySize, SMH256);
    cudaFuncSetAttribute(gemm_ctx, cudaFuncAttributeMaxDynamicSharedMemorySize, SMCTX);

    dim3 tb(32, 8);

    // 1-3. Transpose + fp16-convert all weights into [N,K]
    transpose4_kernel<<<dim3(128, 128, 4), tb>>>(wq, wk, wv, wo, wqT, wkT, wvT, woT);
    transpose_rc_kernel<<<dim3(D_FF / 32, D_MODEL / 32), tb>>>(w_in,  winT, D_MODEL, D_FF);
    transpose_rc_kernel<<<dim3(D_MODEL / 32, D_FF / 32), tb>>>(w_out, wouT, D_FF, D_MODEL);

    // 4. LayerNorm (emits fp16)
    layernorm_kernel<<<NROWS, 256>>>(x, lns, lno, xn);

    // 5-7. QKV projections (fp16; Q,K -> fp16, V -> fp32 tf32-rounded)
    dim3 gP(D_MODEL / 128, NROWS / 256, 1);
    gemm_h<256,0,2,false><<<gP, 256, SMH256>>>(xn, wqT, q, nullptr, nullptr,
        D_MODEL, D_MODEL, D_MODEL, D_MODEL, 0, 0, 0, 0, 0, 0, 1);
    gemm_h<256,0,2,false><<<gP, 256, SMH256>>>(xn, wkT, k, nullptr, nullptr,
        D_MODEL, D_MODEL, D_MODEL, D_MODEL, 0, 0, 0, 0, 0, 0, 1);
    gemm_h<256,0,1,false><<<gP, 256, SMH256>>>(xn, wvT, v, nullptr, nullptr,
        D_MODEL, D_MODEL, D_MODEL, D_MODEL, 0, 0, 0, 0, 0, 0, 1);

    // 8. RoPE (fp16)
    {
        int total = NROWS * N_HEADS * (ROTARY / 2);
        rope_kernel<<<(total + 255) / 256, 256>>>(q, k);
    }

    // 9. scores = q @ k^T (fp16, causal tile-skip, batched b,h; C fp32)
    dim3 gS(SEQ / 128, SEQ / 128, BATCH * N_HEADS);
    gemm_h<128,0,0,true ><<<gS, 256, SMH128>>>(q, k, sc, nullptr, nullptr,
        D_HEAD, D_MODEL, D_MODEL, SEQ,
        (long)SEQ * D_MODEL, (long)D_HEAD,
        (long)SEQ * D_MODEL, (long)D_HEAD,
        (long)N_HEADS * SEQ * SEQ, (long)SEQ * SEQ, N_HEADS);

    // 10. causal softmax (fp32, emits tf32 probs)
    softmax_kernel<<<BATCH * N_HEADS * SEQ, 256>>>(sc);

    // 11. ctx = probs @ v (tf32 scalar path, K truncated; C fp16)
    dim3 gC(D_HEAD / 128, SEQ / 128, BATCH * N_HEADS);
    gemm_ctx<<<gC, 256, SMCTX>>>(sc, v, ctx,
        SEQ, SEQ, D_MODEL, D_MODEL,
        (long)N_HEADS * SEQ * SEQ, (long)SEQ * SEQ,
        (long)SEQ * D_MODEL, (long)D_HEAD,
        (long)SEQ * D_MODEL, (long)D_HEAD, N_HEADS);

    // 12. x2 = x + ctx @ wo (fp16 GEMM, fp32 residual, C fp32)
    gemm_h<256,2,0,false><<<gP, 256, SMH256>>>(ctx, woT, x2, nullptr, x,
        D_MODEL, D_MODEL, D_MODEL, D_MODEL, 0, 0, 0, 0, 0, 0, 1);

    // 13. LayerNorm 2 (emits fp16)
    layernorm_kernel<<<NROWS, 256>>>(x2, lns, lno, xn2);

    // 14. h = gelu(xn2 @ w_in + b_in) (fp16 GEMM; C fp16)
    dim3 gF(D_FF / 128, NROWS / 256, 1);
    gemm_h<256,1,2,false><<<gF, 256, SMH256>>>(xn2, winT, hbuf, b_in, nullptr,
        D_MODEL, D_MODEL, D_MODEL, D_FF, 0, 0, 0, 0, 0, 0, 1);

    // 15. out = x2 + h @ w_out + b_out (fp16 GEMM; C fp32)
    gemm_h<256,3,0,false><<<gP, 256, SMH256>>>(hbuf, wouT, out, b_out, x2,
        D_FF, D_FF, D_FF, D_MODEL, 0, 0, 0, 0, 0, 0, 1);
}

// round 9
// speedup vs baseline: 2.2593x; 1.1774x over previous
#include <cuda_runtime.h>
#include <cuda_fp16.h>
#include <cstdint>
#include <math.h>

#define D_MODEL 4096
#define N_HEADS 16
#define D_HEAD  256
#define ROTARY  64
#define D_FF    16384
#define BATCH   2
#define SEQ     2048
#define NROWS   (BATCH*SEQ)   /* 4096 */

#define STAGES 3
/* fp16 GEMM: BK=64 halfs, row stride 72 halfs = 144B (LDSM conflict-free) */
#define ROWB 144
#define STGB (128 * ROWB)          /* per-stage bytes per operand: 18,432 */
#define SMH  (STAGES * 2 * STGB)   /* 110,592 */

// ---------------------------------------------------------------------------
// Scratch (static device globals; no allocation allowed)
// ---------------------------------------------------------------------------
__device__ __align__(16) __half g_xn [(size_t)NROWS * D_MODEL];
__device__ __align__(16) __half g_xn2[(size_t)NROWS * D_MODEL];
__device__ __align__(16) __half g_q  [(size_t)NROWS * D_MODEL];
__device__ __align__(16) __half g_k  [(size_t)NROWS * D_MODEL];
__device__ __align__(16) __half g_v  [(size_t)NROWS * D_MODEL];
__device__ __align__(16) __half g_vt [(size_t)NROWS * D_MODEL];   // per-head V^T
__device__ __align__(16) __half g_ctx[(size_t)NROWS * D_MODEL];
__device__ __align__(16) __half g_h  [(size_t)NROWS * D_FF];
__device__ __align__(16) __half g_p  [(size_t)BATCH * N_HEADS * SEQ * SEQ]; // 256 MB probs
__device__ __align__(16) __half g_wh [(size_t)201326592];                   // 384 MB W^T fp16
__device__ __align__(16) float  g_x2 [(size_t)NROWS * D_MODEL];
__device__ __align__(16) float  g_sc [(size_t)BATCH * N_HEADS * SEQ * SEQ]; // 512 MB scores

// ---------------------------------------------------------------------------
// Helpers
// ---------------------------------------------------------------------------
__device__ __forceinline__ float gelu_f(float x) {
    return 0.5f * x * (1.0f + tanhf(0.7978845608028654f * (x + 0.044715f * x * x * x)));
}
__device__ __forceinline__ void cp16(uint32_t dst, const void* src) {
    asm volatile("cp.async.cg.shared.global [%0], [%1], 16;\n" :: "r"(dst), "l"(src));
}
__device__ __forceinline__ void cp_commit() {
    asm volatile("cp.async.commit_group;\n" ::: "memory");
}
__device__ __forceinline__ void cp_wait1() {
    asm volatile("cp.async.wait_group 1;\n" ::: "memory");
}
__device__ __forceinline__ void ldsm4(uint32_t& r0, uint32_t& r1, uint32_t& r2, uint32_t& r3,
                                      uint32_t addr) {
    asm volatile("ldmatrix.sync.aligned.m8n8.x4.shared.b16 {%0,%1,%2,%3}, [%4];"
                 : "=r"(r0), "=r"(r1), "=r"(r2), "=r"(r3) : "r"(addr));
}

// ---------------------------------------------------------------------------
// Weight transpose + fp16 convert: out[c][r] = half(in[r][c])
// ---------------------------------------------------------------------------
__global__ void transpose4_kernel(const float* __restrict__ w0, const float* __restrict__ w1,
                                  const float* __restrict__ w2, const float* __restrict__ w3,
                                  __half* __restrict__ o0, __half* __restrict__ o1,
                                  __half* __restrict__ o2, __half* __restrict__ o3)
{
    __shared__ float tile[32][33];
    const float* in; __half* out;
    switch (blockIdx.z) {
        case 0: in = w0; out = o0; break;
        case 1: in = w1; out = o1; break;
        case 2: in = w2; out = o2; break;
        default: in = w3; out = o3; break;
    }
    int x = blockIdx.x * 32 + threadIdx.x;
    int y = blockIdx.y * 32 + threadIdx.y;
#pragma unroll
    for (int j = 0; j < 32; j += 8)
        tile[threadIdx.y + j][threadIdx.x] = in[(size_t)(y + j) * 4096 + x];
    __syncthreads();
    x = blockIdx.y * 32 + threadIdx.x;
    y = blockIdx.x * 32 + threadIdx.y;
#pragma unroll
    for (int j = 0; j < 32; j += 8)
        out[(size_t)(y + j) * 4096 + x] = __float2half_rn(tile[threadIdx.x][threadIdx.y + j]);
}

__global__ void transpose_rc_kernel(const float* __restrict__ in, __half* __restrict__ out,
                                    int R, int C)
{
    __shared__ float tile[32][33];
    int x = blockIdx.x * 32 + threadIdx.x;
    int y = blockIdx.y * 32 + threadIdx.y;
#pragma unroll
    for (int j = 0; j < 32; j += 8)
        tile[threadIdx.y + j][threadIdx.x] = in[(size_t)(y + j) * C + x];
    __syncthreads();
    x = blockIdx.y * 32 + threadIdx.x;
    y = blockIdx.x * 32 + threadIdx.y;
#pragma unroll
    for (int j = 0; j < 32; j += 8)
        out[(size_t)(y + j) * R + x] = __float2half_rn(tile[threadIdx.x][threadIdx.y + j]);
}

// V [bt][h*256+d] fp16  ->  Vt [(b*4096 + h*256 + d)][s] fp16 (k-contiguous per head)
__global__ void transpose_v_kernel(const __half* __restrict__ in, __half* __restrict__ out)
{
    __shared__ __half tile[32][33];
    int x = blockIdx.x * 32 + threadIdx.x;    // dmodel col
    int y = blockIdx.y * 32 + threadIdx.y;    // bt row
#pragma unroll
    for (int j = 0; j < 32; j += 8)
        tile[threadIdx.y + j][threadIdx.x] = in[(size_t)(y + j) * D_MODEL + x];
    __syncthreads();
    int d0 = blockIdx.x * 32 + threadIdx.y;   // dmodel index base
    int yo = blockIdx.y * 32 + threadIdx.x;   // bt index
    int b = yo >> 11, s = yo & (SEQ - 1);
#pragma unroll
    for (int j = 0; j < 32; j += 8) {
        int d = d0 + j;
        out[((size_t)(b * D_MODEL + d)) * SEQ + s] = tile[threadIdx.x][threadIdx.y + j];
    }
}

// ---------------------------------------------------------------------------
// LayerNorm: one block per row; emits fp16
// ---------------------------------------------------------------------------
__global__ void layernorm_kernel(const float* __restrict__ x,
                                 const float* __restrict__ scale,
                                 const float* __restrict__ offset,
                                 __half* __restrict__ out)
{
    int row = blockIdx.x;
    const float4* xr = reinterpret_cast<const float4*>(x + (size_t)row * D_MODEL);
    float4 vals[4];
    float s = 0.f, sq = 0.f;
#pragma unroll
    for (int p = 0; p < 4; p++) {
        float4 v = xr[threadIdx.x + p * 256];
        vals[p] = v;
        s  += v.x + v.y + v.z + v.w;
        sq += v.x*v.x + v.y*v.y + v.z*v.z + v.w*v.w;
    }
    __shared__ float shm[64];
#pragma unroll
    for (int o = 16; o > 0; o >>= 1) {
        s  += __shfl_xor_sync(0xffffffffu, s,  o);
        sq += __shfl_xor_sync(0xffffffffu, sq, o);
    }
    int w = threadIdx.x >> 5;
    if ((threadIdx.x & 31) == 0) { shm[w] = s; shm[w + 32] = sq; }
    __syncthreads();
    if (threadIdx.x < 32) {
        float a = (threadIdx.x < 8) ? shm[threadIdx.x]      : 0.f;
        float b = (threadIdx.x < 8) ? shm[32 + threadIdx.x] : 0.f;
#pragma unroll
        for (int o = 4; o > 0; o >>= 1) {
            a += __shfl_xor_sync(0xffffffffu, a, o);
            b += __shfl_xor_sync(0xffffffffu, b, o);
        }
        if (threadIdx.x == 0) { shm[0] = a; shm[1] = b; }
    }
    __syncthreads();
    float mean = shm[0] * (1.0f / D_MODEL);
    float var  = shm[1] * (1.0f / D_MODEL) - mean * mean;
    float inv  = rsqrtf(var + 1e-5f);
    const float4* sc4 = reinterpret_cast<const float4*>(scale);
    const float4* of4 = reinterpret_cast<const float4*>(offset);
    __half2* o2 = reinterpret_cast<__half2*>(out + (size_t)row * D_MODEL);
#pragma unroll
    for (int p = 0; p < 4; p++) {
        int i = threadIdx.x + p * 256;
        float4 v = vals[p], g = sc4[i], b = of4[i];
        o2[i * 2]     = __floats2half2_rn((v.x - mean) * inv * g.x + b.x,
                                          (v.y - mean) * inv * g.y + b.y);
        o2[i * 2 + 1] = __floats2half2_rn((v.z - mean) * inv * g.z + b.z,
                                          (v.w - mean) * inv * g.w + b.w);
    }
}

// ---------------------------------------------------------------------------
// RoPE on fp16 q, k (compute fp32, store fp16)
// ---------------------------------------------------------------------------
__global__ void rope_kernel(__half* __restrict__ q, __half* __restrict__ k)
{
    const int HALF = ROTARY / 2;
    int idx = blockIdx.x * blockDim.x + threadIdx.x;
    int total = NROWS * N_HEADS * HALF;
    if (idx >= total) return;
    int i  = idx % HALF;
    int h  = (idx / HALF) % N_HEADS;
    int bt = idx / (HALF * N_HEADS);
    int t  = bt % SEQ;

    float inv_freq = powf(10000.0f, -(float)i / (float)HALF);
    float fr = (float)t * inv_freq;
    float sn, cs;
    sincosf(fr, &sn, &cs);

    size_t base = (size_t)bt * D_MODEL + (size_t)h * D_HEAD + 2 * i;
    __half2* qp = reinterpret_cast<__half2*>(q + base);
    __half2* kp = reinterpret_cast<__half2*>(k + base);
    float2 qv = __half22float2(*qp);
    float2 kv = __half22float2(*kp);
    *qp = __floats2half2_rn(qv.x * cs - qv.y * sn, qv.y * cs + qv.x * sn);
    *kp = __floats2half2_rn(kv.x * cs - kv.y * sn, kv.y * cs + kv.x * sn);
}

// ---------------------------------------------------------------------------
// Causal softmax: reads fp32 scores, writes fp16 probs.
// Skips chunks beyond the causal tile boundary (never read by ctx GEMM).
// ---------------------------------------------------------------------------
__global__ void softmax_kernel(const float* __restrict__ scores, __half* __restrict__ probs)
{
    size_t r = blockIdx.x;
    int t = blockIdx.x % SEQ;
    const float* row = scores + r * SEQ;
    __half* prow = probs + r * SEQ;
    const float sc = 1.0f / 16.0f;
    int bound = ((t >> 7) + 1) << 7;

    float v[8];
    float mx = -1e30f;
#pragma unroll
    for (int j = 0; j < 8; j++) {
        int col = threadIdx.x + j * 256;
        float xv = (col <= t) ? row[col] * sc : -1e30f;
        v[j] = xv;
        mx = fmaxf(mx, xv);
    }
    __shared__ float shm[32];
#pragma unroll
    for (int o = 16; o > 0; o >>= 1) mx = fmaxf(mx, __shfl_xor_sync(0xffffffffu, mx, o));
    if ((threadIdx.x & 31) == 0) shm[threadIdx.x >> 5] = mx;
    __syncthreads();
    if (threadIdx.x < 32) {
        float m = (threadIdx.x < 8) ? shm[threadIdx.x] : -1e30f;
#pragma unroll
        for (int o = 4; o > 0; o >>= 1) m = fmaxf(m, __shfl_xor_sync(0xffffffffu, m, o));
        if (threadIdx.x == 0) shm[0] = m;
    }
    __syncthreads();
    mx = shm[0];
    __syncthreads();

    float s = 0.f;
#pragma unroll
    for (int j = 0; j < 8; j++) { float e = expf(v[j] - mx); v[j] = e; s += e; }
#pragma unroll
    for (int o = 16; o > 0; o >>= 1) s += __shfl_xor_sync(0xffffffffu, s, o);
    if ((threadIdx.x & 31) == 0) shm[threadIdx.x >> 5] = s;
    __syncthreads();
    if (threadIdx.x < 32) {
        float a = (threadIdx.x < 8) ? shm[threadIdx.x] : 0.f;
#pragma unroll
        for (int o = 4; o > 0; o >>= 1) a += __shfl_xor_sync(0xffffffffu, a, o);
        if (threadIdx.x == 0) shm[0] = a;
    }
    __syncthreads();
    float inv = 1.0f / shm[0];
#pragma unroll
    for (int j = 0; j < 8; j++) {
        if (j * 256 < bound)
            prow[threadIdx.x + j * 256] = __float2half_rn(v[j] * inv);
    }
}

// ---------------------------------------------------------------------------
// FP16 tensor-core GEMM: C[M,N] = A[M,K] @ Bt[N,K]^T (+epi)
//   128x128 CTA tile, __launch_bounds__(256,2) -> 2 CTAs/SM (16 warps).
//   m16n8k16 MMA, fragments via ldmatrix.b16; cp.async 3-stage, BK=64 halfs.
//   EPI: 0 none | 1 bias+gelu | 2 +Res | 3 bias+Res
//   OUT: 0 f32 | 2 fp16
//   CSKIP: causal tile skip (scores).  CKT: causal K truncation (ctx).
// ---------------------------------------------------------------------------
template<int EPI, int OUT, bool CSKIP, bool CKT>
__global__ void __launch_bounds__(256, 2)
gemm_h(const __half* __restrict__ A, const __half* __restrict__ Bt,
       void* __restrict__ Cv, const float* __restrict__ bias,
       const float* __restrict__ Res,
       int K, int lda, int ldb, int ldc,
       long sAb, long sAh, long sBb, long sBh, long sCb, long sCh, int Hb)
{
    int m0 = blockIdx.y * 128;
    int n0 = blockIdx.x * 128;
    if (CSKIP) { if (n0 > m0 + 127) return; }

    int z = blockIdx.z;
    int b = z / Hb, hh = z % Hb;
    A  += (size_t)b * sAb + (size_t)hh * sAh;
    Bt += (size_t)b * sBb + (size_t)hh * sBh;
    float*  Cf = reinterpret_cast<float*>(Cv)  + (size_t)b * sCb + (size_t)hh * sCh;
    __half* Ch = reinterpret_cast<__half*>(Cv) + (size_t)b * sCb + (size_t)hh * sCh;

    extern __shared__ char smem_dyn[];
    uint32_t aBase = (uint32_t)__cvta_generic_to_shared(smem_dyn);
    uint32_t bBase = aBase + STAGES * STGB;

    int tid = threadIdx.x;
    int lane = tid & 31, warp = tid >> 5;
    int wm = warp & 3, wn = warp >> 2;
    int g  = lane >> 2, tg = lane & 3;

    float acc[2][8][4] = {};

    int KT = K >> 6;
    if (CKT) { int lim = (m0 + 128) >> 6; if (lim < KT) KT = lim; }

    int lc = tid & 7, lr = tid >> 3;       // load: 8 chunks/row, 32 rows/pass

    auto loadTile = [&](int kt, int s) {
        const __half* ap = A + (size_t)m0 * lda + (size_t)kt * 64;
#pragma unroll
        for (int p = 0; p < 4; p++) {
            int row = lr + p * 32;
            cp16(aBase + (uint32_t)(s * STGB + row * ROWB + lc * 16),
                 ap + (size_t)row * lda + lc * 8);
        }
        const __half* bp = Bt + (size_t)n0 * ldb + (size_t)kt * 64;
#pragma unroll
        for (int p = 0; p < 4; p++) {
            int row = lr + p * 32;
            cp16(bBase + (uint32_t)(s * STGB + row * ROWB + lc * 16),
                 bp + (size_t)row * ldb + lc * 8);
        }
    };

    loadTile(0, 0); cp_commit();
    if (KT > 1) loadTile(1, 1);
    cp_commit();

    int lane_row = (lane & 7) | (((lane >> 3) & 1) << 3);  // 0..15
    int lane_kb  = (lane >> 4) << 4;                        // 0 or 16 bytes
    uint32_t aoff0 = (uint32_t)((wm * 32 + lane_row) * ROWB + lane_kb);
    uint32_t boff0 = (uint32_t)((wn * 64 + lane_row) * ROWB + lane_kb);

    for (int kt = 0; kt < KT; kt++) {
        cp_wait1();
        __syncthreads();
        int s = kt % STAGES;
        uint32_t aS = aBase + (uint32_t)(s * STGB) + aoff0;
        uint32_t bS = bBase + (uint32_t)(s * STGB) + boff0;

#pragma unroll
        for (int kk = 0; kk < 4; kk++) {
            uint32_t af[2][4], bf[8][2];
            uint32_t kkb = kk * 32;
#pragma unroll
            for (int mt = 0; mt < 2; mt++)
                ldsm4(af[mt][0], af[mt][1], af[mt][2], af[mt][3],
                      aS + (uint32_t)(mt * 16 * ROWB) + kkb);
#pragma unroll
            for (int p = 0; p < 4; p++)
                ldsm4(bf[2*p][0], bf[2*p+1][0], bf[2*p][1], bf[2*p+1][1],
                      bS + (uint32_t)(p * 16 * ROWB) + kkb);
#pragma unroll
            for (int mt = 0; mt < 2; mt++)
#pragma unroll
                for (int nt = 0; nt < 8; nt++) {
                    asm volatile(
                        "mma.sync.aligned.m16n8k16.row.col.f32.f16.f16.f32 "
                        "{%0,%1,%2,%3}, {%4,%5,%6,%7}, {%8,%9}, {%0,%1,%2,%3};\n"
                        : "+f"(acc[mt][nt][0]), "+f"(acc[mt][nt][1]),
                          "+f"(acc[mt][nt][2]), "+f"(acc[mt][nt][3])
                        : "r"(af[mt][0]), "r"(af[mt][1]), "r"(af[mt][2]), "r"(af[mt][3]),
                          "r"(bf[nt][0]), "r"(bf[nt][1]));
                }
        }

        if (kt + 2 < KT) loadTile(kt + 2, (kt + 2) % STAGES);
        cp_commit();
    }

    // Epilogue
#pragma unroll
    for (int mt = 0; mt < 2; mt++) {
#pragma unroll
        for (int nt = 0; nt < 8; nt++) {
            int row0 = m0 + wm * 32 + mt * 16 + g;
            int col  = n0 + wn * 64 + nt * 8 + 2 * tg;
#pragma unroll
            for (int rr = 0; rr < 2; rr++) {
                int row = row0 + rr * 8;
                float v0 = acc[mt][nt][rr * 2 + 0];
                float v1 = acc[mt][nt][rr * 2 + 1];
                if (EPI == 1) {
                    v0 = gelu_f(v0 + bias[col]);
                    v1 = gelu_f(v1 + bias[col + 1]);
                } else if (EPI == 2) {
                    float2 rv = *reinterpret_cast<const float2*>(&Res[(size_t)row * ldc + col]);
                    v0 += rv.x; v1 += rv.y;
                } else if (EPI == 3) {
                    float2 rv = *reinterpret_cast<const float2*>(&Res[(size_t)row * ldc + col]);
                    v0 += bias[col] + rv.x; v1 += bias[col + 1] + rv.y;
                }
                if (OUT == 2) {
                    *reinterpret_cast<__half2*>(&Ch[(size_t)row * ldc + col]) =
                        __floats2half2_rn(v0, v1);
                } else {
                    float2 ov; ov.x = v0; ov.y = v1;
                    *reinterpret_cast<float2*>(&Cf[(size_t)row * ldc + col]) = ov;
                }
            }
        }
    }
}

// ---------------------------------------------------------------------------
// Launch
// ---------------------------------------------------------------------------
extern "C" void kernel_launch(void* const* d_in, const int* in_sizes, int n_in,
                              void* d_out, int out_size)
{
    (void)in_sizes; (void)n_in; (void)out_size;
    const float* x     = (const float*)d_in[0];
    const float* lns   = (const float*)d_in[1];
    const float* lno   = (const float*)d_in[2];
    const float* wq    = (const float*)d_in[3];
    const float* wk    = (const float*)d_in[4];
    const float* wv    = (const float*)d_in[5];
    const float* wo    = (const float*)d_in[6];
    const float* w_in  = (const float*)d_in[7];
    const float* b_in  = (const float*)d_in[8];
    const float* w_out = (const float*)d_in[9];
    const float* b_out = (const float*)d_in[10];
    float* out = (float*)d_out;

    __half *xn, *xn2, *q, *k, *v, *vt, *ctx, *hbuf, *p, *wh;
    float *x2, *sc;
    cudaGetSymbolAddress((void**)&xn,   g_xn);
    cudaGetSymbolAddress((void**)&xn2,  g_xn2);
    cudaGetSymbolAddress((void**)&q,    g_q);
    cudaGetSymbolAddress((void**)&k,    g_k);
    cudaGetSymbolAddress((void**)&v,    g_v);
    cudaGetSymbolAddress((void**)&vt,   g_vt);
    cudaGetSymbolAddress((void**)&ctx,  g_ctx);
    cudaGetSymbolAddress((void**)&hbuf, g_h);
    cudaGetSymbolAddress((void**)&p,    g_p);
    cudaGetSymbolAddress((void**)&wh,   g_wh);
    cudaGetSymbolAddress((void**)&x2,   g_x2);
    cudaGetSymbolAddress((void**)&sc,   g_sc);

    const size_t WSZ = (size_t)D_MODEL * D_MODEL;
    __half* wqT  = wh;
    __half* wkT  = wh + WSZ;
    __half* wvT  = wh + 2 * WSZ;
    __half* woT  = wh + 3 * WSZ;
    __half* winT = wh + 4 * WSZ;                    // [D_FF, D_MODEL]
    __half* wouT = winT + (size_t)D_MODEL * D_FF;   // [D_MODEL, D_FF]

    cudaFuncSetAttribute(gemm_h<0,2,false,false>, cudaFuncAttributeMaxDynamicSharedMemorySize, SMH);
    cudaFuncSetAttribute(gemm_h<0,0,true ,false>, cudaFuncAttributeMaxDynamicSharedMemorySize, SMH);
    cudaFuncSetAttribute(gemm_h<0,2,false,true >, cudaFuncAttributeMaxDynamicSharedMemorySize, SMH);
    cudaFuncSetAttribute(gemm_h<2,0,false,false>, cudaFuncAttributeMaxDynamicSharedMemorySize, SMH);
    cudaFuncSetAttribute(gemm_h<1,2,false,false>, cudaFuncAttributeMaxDynamicSharedMemorySize, SMH);
    cudaFuncSetAttribute(gemm_h<3,0,false,false>, cudaFuncAttributeMaxDynamicSharedMemorySize, SMH);

    dim3 tb(32, 8);

    // 1-3. Transpose + fp16-convert all weights into [N,K]
    transpose4_kernel<<<dim3(128, 128, 4), tb>>>(wq, wk, wv, wo, wqT, wkT, wvT, woT);
    transpose_rc_kernel<<<dim3(D_FF / 32, D_MODEL / 32), tb>>>(w_in,  winT, D_MODEL, D_FF);
    transpose_rc_kernel<<<dim3(D_MODEL / 32, D_FF / 32), tb>>>(w_out, wouT, D_FF, D_MODEL);

    // 4. LayerNorm (emits fp16)
    layernorm_kernel<<<NROWS, 256>>>(x, lns, lno, xn);

    // 5-7. QKV projections (all fp16 out)
    dim3 gP(D_MODEL / 128, NROWS / 128, 1);
    gemm_h<0,2,false,false><<<gP, 256, SMH>>>(xn, wqT, q, nullptr, nullptr,
        D_MODEL, D_MODEL, D_MODEL, D_MODEL, 0, 0, 0, 0, 0, 0, 1);
    gemm_h<0,2,false,false><<<gP, 256, SMH>>>(xn, wkT, k, nullptr, nullptr,
        D_MODEL, D_MODEL, D_MODEL, D_MODEL, 0, 0, 0, 0, 0, 0, 1);
    gemm_h<0,2,false,false><<<gP, 256, SMH>>>(xn, wvT, v, nullptr, nullptr,
        D_MODEL, D_MODEL, D_MODEL, D_MODEL, 0, 0, 0, 0, 0, 0, 1);

    // 8. RoPE (fp16)
    {
        int total = NROWS * N_HEADS * (ROTARY / 2);
        rope_kernel<<<(total + 255) / 256, 256>>>(q, k);
    }

    // 9. Per-head V transpose -> Vt (k-contiguous)
    transpose_v_kernel<<<dim3(D_MODEL / 32, NROWS / 32), tb>>>(v, vt);

    // 10. scores = q @ k^T (causal tile-skip, batched b,h; C fp32)
    dim3 gS(SEQ / 128, SEQ / 128, BATCH * N_HEADS);
    gemm_h<0,0,true ,false><<<gS, 256, SMH>>>(q, k, sc, nullptr, nullptr,
        D_HEAD, D_MODEL, D_MODEL, SEQ,
        (long)SEQ * D_MODEL, (long)D_HEAD,
        (long)SEQ * D_MODEL, (long)D_HEAD,
        (long)N_HEADS * SEQ * SEQ, (long)SEQ * SEQ, N_HEADS);

    // 11. causal softmax (fp32 scores -> fp16 probs)
    softmax_kernel<<<BATCH * N_HEADS * SEQ, 256>>>(sc, p);

    // 12. ctx = probs @ Vt^T (fp16, causal K-trunc; C fp16)
    dim3 gC(D_HEAD / 128, SEQ / 128, BATCH * N_HEADS);
    gemm_h<0,2,false,true ><<<gC, 256, SMH>>>(p, vt, ctx, nullptr, nullptr,
        SEQ, SEQ, SEQ, D_MODEL,
        (long)N_HEADS * SEQ * SEQ, (long)SEQ * SEQ,
        (long)N_HEADS * D_HEAD * SEQ, (long)D_HEAD * SEQ,
        (long)SEQ * D_MODEL, (long)D_HEAD, N_HEADS);

    // 13. x2 = x + ctx @ wo (C fp32)
    gemm_h<2,0,false,false><<<gP, 256, SMH>>>(ctx, woT, x2, nullptr, x,
        D_MODEL, D_MODEL, D_MODEL, D_MODEL, 0, 0, 0, 0, 0, 0, 1);

    // 14. LayerNorm 2 (emits fp16)
    layernorm_kernel<<<NROWS, 256>>>(x2, lns, lno, xn2);

    // 15. h = gelu(xn2 @ w_in + b_in) (C fp16)
    dim3 gF(D_FF / 128, NROWS / 128, 1);
    gemm_h<1,2,false,false><<<gF, 256, SMH>>>(xn2, winT, hbuf, b_in, nullptr,
        D_MODEL, D_MODEL, D_MODEL, D_FF, 0, 0, 0, 0, 0, 0, 1);

    // 16. out = x2 + h @ w_out + b_out (C fp32)
    gemm_h<3,0,false,false><<<gP, 256, SMH>>>(hbuf, wouT, out, b_out, x2,
        D_FF, D_FF, D_FF, D_MODEL, 0, 0, 0, 0, 0, 0, 1);
}